// round 7
// baseline (speedup 1.0000x reference)
#include <cuda_runtime.h>
#include <cuda_bf16.h>

// B=4, H=16, L=8192, D=64
#define BH_    64
#define H_     16
#define L_     8192
#define D_     64
#define TILE_  128                 // positions per tile (block)
#define PPW_   16                  // positions per warp
#define WPB_   8                   // warps per block
#define NT_    64                  // tiles per (b,h) chain
#define NBLK_  (BH_ * NT_)         // 4096
#define LBW_   8                   // lookback window
#define EPS_   1e-6f

// Decoupled-lookback state. flag: 0 = none, 1 = aggregate, 2 = inclusive.
__device__ int   g_ticket;
__device__ int   g_flag[NBLK_];
__device__ float g_aggr[(size_t)NBLK_ * 128];   // [64 k-sum | 64 kv-sum]
__device__ float g_incl[(size_t)NBLK_ * 128];

__device__ __forceinline__ float phi(float x) {
    return x > 0.0f ? x + 1.0f : __expf(x);
}

__global__ void la_reset() {
    int i = blockIdx.x * blockDim.x + threadIdx.x;
    if (i < NBLK_) g_flag[i] = 0;
    if (i == 0) g_ticket = 0;
}

// ---------------------------------------------------------------------------
// Fused single-pass scan. TILE_=128: resident k,v footprint ~47MB stays L2-hot
// for the phase-C re-read; windowed lookback consumes up to 8 predecessors per
// round. Warp w owns positions [w*16, w*16+16); lane owns channels 2*lane,
// 2*lane+1. Scan channel space: c<64 = k-state, c>=64 = kv-state.
// ---------------------------------------------------------------------------
__global__ void __launch_bounds__(256, 5) la_fused(
    const float* __restrict__ qp, const float* __restrict__ kp,
    const float* __restrict__ vp, const float* __restrict__ mp,
    float* __restrict__ op)
{
    __shared__ float s_warp[WPB_][128];  // warp sums -> exclusive warp prefixes
    __shared__ float s_tot[128];         // tile totals
    __shared__ float s_chain[128];       // exclusive chain prefix
    __shared__ int   s_tile;
    __shared__ int   s_f[LBW_];

    const int t = threadIdx.x;
    if (t == 0) s_tile = atomicAdd(&g_ticket, 1);
    __syncthreads();
    const int tile = s_tile;
    const int bh   = tile & (BH_ - 1);     // chain-interleaved ticket mapping
    const int ti   = tile >> 6;
    const int b    = bh >> 4;
    const int w    = t >> 5;
    const int lane = t & 31;
    const int l0   = ti * TILE_ + w * PPW_;
    const size_t base = ((size_t)bh * L_ + l0) * D_ + lane * 2;
    const float* mrow = mp + b * L_ + l0;

    // ---- Phase A: stream k,v; accumulate warp sums ----
    {
        float sk0 = 0.f, sk1 = 0.f, sv0 = 0.f, sv1 = 0.f;
        #pragma unroll
        for (int i = 0; i < PPW_; ++i) {
            float2 kk = *(const float2*)(kp + base + (size_t)i * D_);
            float2 vv = *(const float2*)(vp + base + (size_t)i * D_);
            float  m  = mrow[i];
            float a0 = phi(kk.x) * m, a1 = phi(kk.y) * m;
            sk0 += a0; sk1 += a1;
            sv0 += a0 * (vv.x * m); sv1 += a1 * (vv.y * m);
        }
        s_warp[w][2 * lane]          = sk0;
        s_warp[w][2 * lane + 1]      = sk1;
        s_warp[w][64 + 2 * lane]     = sv0;
        s_warp[w][64 + 2 * lane + 1] = sv1;
    }
    __syncthreads();

    // ---- Intra-tile scan over the 8 warps (threads 0..127, one channel) ----
    if (t < 128) {
        float run = 0.f;
        #pragma unroll
        for (int g2 = 0; g2 < WPB_; ++g2) {
            float x = s_warp[g2][t]; s_warp[g2][t] = run; run += x;
        }
        s_tot[t] = run;
        if (ti > 0) g_aggr[(size_t)tile * 128 + t] = run;
        s_chain[t] = 0.f;
    }
    __syncthreads();
    if (ti > 0) {
        __threadfence();
        if (t == 0) atomicExch(&g_flag[tile], 1);
    }

    // ---- Windowed decoupled lookback (consume up to LBW_ per round) ----
    if (ti > 0) {
        volatile int* vf = (volatile int*)g_flag;
        int p = tile - BH_;                 // nearest predecessor
        for (;;) {
            const int pti = (p >> 6);       // its tile index in chain
            if (t == 0) {
                int f;
                while ((f = vf[p]) == 0) __nanosleep(64);
                s_f[0] = f;
            } else if (t < LBW_ && pti - t >= 0) {
                s_f[t] = vf[p - t * BH_];   // opportunistic snapshot
            }
            __syncthreads();
            // Decide how many entries to consume this round (all threads agree)
            int n = 1, lastf = s_f[0];
            if (lastf != 2) {
                #pragma unroll
                for (int j = 1; j < LBW_; ++j) {
                    if (pti - j < 0) break;
                    int fj = s_f[j];
                    if (fj == 0) break;
                    n = j + 1; lastf = fj;
                    if (fj == 2) break;
                }
            }
            __threadfence();   // acquire: payload reads after flag reads
            if (t < 128) {
                float acc = 0.f;
                for (int j = 0; j < n - 1; ++j)
                    acc += g_aggr[(size_t)(p - j * BH_) * 128 + t];
                acc += (lastf == 2)
                     ? g_incl[(size_t)(p - (n - 1) * BH_) * 128 + t]
                     : g_aggr[(size_t)(p - (n - 1) * BH_) * 128 + t];
                s_chain[t] += acc;
            }
            if (lastf == 2) break;
            p -= n * BH_;
            __syncthreads();
        }
    }
    __syncthreads();

    // ---- Publish inclusive prefix for successors ----
    if (t < 128) g_incl[(size_t)tile * 128 + t] = s_chain[t] + s_tot[t];
    __syncthreads();
    __threadfence();
    if (t == 0) atomicExch(&g_flag[tile], 2);

    // ---- Phase C: re-read own k,v (L2-hot), finish scan, compute z, output ----
    float2 pk  = make_float2(s_chain[2 * lane]      + s_warp[w][2 * lane],
                             s_chain[2 * lane + 1]  + s_warp[w][2 * lane + 1]);
    float2 pkv = make_float2(s_chain[64 + 2 * lane]     + s_warp[w][64 + 2 * lane],
                             s_chain[64 + 2 * lane + 1] + s_warp[w][64 + 2 * lane + 1]);

    #pragma unroll 4
    for (int i = 0; i < PPW_; ++i) {
        const size_t off = base + (size_t)i * D_;
        float2 kk = *(const float2*)(kp + off);
        float2 vv = *(const float2*)(vp + off);
        float2 qq = *(const float2*)(qp + off);
        float  m  = mrow[i];

        float a0 = phi(kk.x) * m, a1 = phi(kk.y) * m;
        pk.x += a0; pk.y += a1;
        pkv.x += a0 * (vv.x * m); pkv.y += a1 * (vv.y * m);

        float q0 = phi(qq.x), q1 = phi(qq.y);
        float z = q0 * pk.x + q1 * pk.y;
        z += __shfl_xor_sync(0xffffffffu, z, 16);
        z += __shfl_xor_sync(0xffffffffu, z, 8);
        z += __shfl_xor_sync(0xffffffffu, z, 4);
        z += __shfl_xor_sync(0xffffffffu, z, 2);
        z += __shfl_xor_sync(0xffffffffu, z, 1);
        z = (z + EPS_) * m;
        float rz = 1.0f / z;

        float2 o = make_float2(q0 * pkv.x * rz, q1 * pkv.y * rz);
        *(float2*)(op + off) = o;
    }
}

// ---------------------------------------------------------------------------
extern "C" void kernel_launch(void* const* d_in, const int* in_sizes, int n_in,
                              void* d_out, int out_size)
{
    const float* q = (const float*)d_in[0];
    const float* k = (const float*)d_in[1];
    const float* v = (const float*)d_in[2];
    const float* m = (const float*)d_in[3];
    float* out = (float*)d_out;

    la_reset<<<(NBLK_ + 255) / 256, 256>>>();
    la_fused<<<NBLK_, 256>>>(q, k, v, m, out);
}

// round 9
// speedup vs baseline: 1.2331x; 1.2331x over previous
#include <cuda_runtime.h>
#include <cuda_bf16.h>

// B=4, H=16, L=8192, D=64
#define BH_    64
#define H_     16
#define L_     8192
#define D_     64
#define TILE_  256                 // positions per tile (block)
#define NT_    32                  // tiles per (b,h) chain
#define NBLK_  (BH_ * NT_)         // 2048
#define EPS_   1e-6f

// Decoupled-lookback state. flag: 0 = none, 1 = aggregate, 2 = inclusive.
__device__ int   g_ticket;
__device__ int   g_flag[NBLK_];
__device__ float g_aggr[(size_t)NBLK_ * 256];   // [128 k-sum | 128 kv-sum]
__device__ float g_incl[(size_t)NBLK_ * 256];

__device__ __forceinline__ float phi(float x) {
    return x > 0.0f ? x + 1.0f : __expf(x);
}

// evict_last load via createpolicy + cache_hint (the sm_103a-legal encoding)
__device__ __forceinline__ unsigned long long mk_evict_last_policy() {
    unsigned long long pol;
    asm("createpolicy.fractional.L2::evict_last.b64 %0, 1.0;" : "=l"(pol));
    return pol;
}
__device__ __forceinline__ float4 ld_keep4(const float* p, unsigned long long pol) {
    float4 r;
    asm("ld.global.nc.L2::cache_hint.v4.f32 {%0,%1,%2,%3}, [%4], %5;"
        : "=f"(r.x), "=f"(r.y), "=f"(r.z), "=f"(r.w) : "l"(p), "l"(pol));
    return r;
}
__device__ __forceinline__ float4 ld_stream4(const float* p) {
    float4 r;
    asm("ld.global.cs.nc.v4.f32 {%0,%1,%2,%3}, [%4];"
        : "=f"(r.x), "=f"(r.y), "=f"(r.z), "=f"(r.w) : "l"(p));
    return r;
}
__device__ __forceinline__ void st_stream4(float* p, float4 v) {
    asm volatile("st.global.cs.v4.f32 [%0], {%1,%2,%3,%4};"
                 :: "l"(p), "f"(v.x), "f"(v.y), "f"(v.z), "f"(v.w) : "memory");
}

__global__ void la_reset() {
    int i = blockIdx.x * blockDim.x + threadIdx.x;
    if (i < NBLK_) g_flag[i] = 0;
    if (i == 0) g_ticket = 0;
}

// ---------------------------------------------------------------------------
// Fused single-pass scan (R4 structure). Phase A loads k,v with an evict_last
// L2 policy so the phase-C re-read hits L2; phase C reads k,v,q streaming and
// writes output streaming so the pinned k,v set keeps its L2 capacity.
// Thread map: g = t>>4 owns positions [g*16, g*16+16); d4 = t&15 owns channel
// quad d4*4..d4*4+3.
// ---------------------------------------------------------------------------
__global__ void __launch_bounds__(256, 4) la_fused(
    const float* __restrict__ qp, const float* __restrict__ kp,
    const float* __restrict__ vp, const float* __restrict__ mp,
    float* __restrict__ op)
{
    __shared__ float s_k [16][128];   // group sums -> exclusive group prefixes
    __shared__ float s_kv[16][128];
    __shared__ float s_tot[256];      // tile totals   [k | kv]
    __shared__ float s_chain[256];    // chain prefix  [k | kv]
    __shared__ int   s_tile, s_msg;

    const int t = threadIdx.x;
    if (t == 0) s_tile = atomicAdd(&g_ticket, 1);
    __syncthreads();
    const int tile = s_tile;
    const int bh   = tile & (BH_ - 1);     // chain-interleaved ticket mapping
    const int ti   = tile >> 6;
    const int b    = bh >> 4;
    const int g    = t >> 4;
    const int d4   = t & 15;
    const int l0   = ti * TILE_ + g * 16;
    const size_t base = ((size_t)bh * L_ + l0) * D_ + d4 * 4;
    const float* mrow = mp + b * L_ + l0;
    const unsigned long long pol = mk_evict_last_policy();

    // ---- Phase A: group sums of masked phi(k), phi(k)*v (evict_last) ----
    float4 sk  = make_float4(0.f, 0.f, 0.f, 0.f);
    float4 skv = make_float4(0.f, 0.f, 0.f, 0.f);
    #pragma unroll 4
    for (int i = 0; i < 16; ++i) {
        float4 kk = ld_keep4(kp + base + (size_t)i * D_, pol);
        float4 vv = ld_keep4(vp + base + (size_t)i * D_, pol);
        float  m  = mrow[i];
        float a0 = phi(kk.x) * m, a1 = phi(kk.y) * m,
              a2 = phi(kk.z) * m, a3 = phi(kk.w) * m;
        sk.x += a0; sk.y += a1; sk.z += a2; sk.w += a3;
        skv.x += a0 * (vv.x * m); skv.y += a1 * (vv.y * m);
        skv.z += a2 * (vv.z * m); skv.w += a3 * (vv.w * m);
    }
    *(float4*)&s_k [g][d4 * 4] = sk;
    *(float4*)&s_kv[g][d4 * 4] = skv;
    __syncthreads();

    // ---- Intra-tile scan over the 16 groups (t<128: k, t>=128: kv) ----
    {
        float run = 0.f;
        if (t < 128) {
            const int c = t;
            #pragma unroll
            for (int g2 = 0; g2 < 16; ++g2) {
                float x = s_k[g2][c]; s_k[g2][c] = run; run += x;
            }
        } else {
            const int c = t - 128;
            #pragma unroll
            for (int g2 = 0; g2 < 16; ++g2) {
                float x = s_kv[g2][c]; s_kv[g2][c] = run; run += x;
            }
        }
        s_tot[t] = run;
        if (ti > 0) g_aggr[(size_t)tile * 256 + t] = run;
    }
    __syncthreads();
    if (ti > 0) {
        __threadfence();
        if (t == 0) atomicExch(&g_flag[tile], 1);
    }

    // ---- Decoupled lookback (single flag per tile; thread 0 polls) ----
    s_chain[t] = 0.f;
    if (ti > 0) {
        volatile int* vf = (volatile int*)g_flag;
        int p = tile - BH_;
        for (;;) {
            if (t == 0) {
                int f;
                while ((f = vf[p]) == 0) __nanosleep(64);
                s_msg = f;
            }
            __syncthreads();
            const int f = s_msg;
            __threadfence();   // acquire: order payload reads after flag read
            if (f == 2) {
                s_chain[t] += g_incl[(size_t)p * 256 + t];
                break;
            }
            s_chain[t] += g_aggr[(size_t)p * 256 + t];
            p -= BH_;
            __syncthreads();
        }
    }
    __syncthreads();

    // ---- Publish inclusive prefix for successors ----
    g_incl[(size_t)tile * 256 + t] = s_chain[t] + s_tot[t];
    __syncthreads();
    __threadfence();
    if (t == 0) atomicExch(&g_flag[tile], 2);

    // ---- Phase C: re-read own k,v from L2 (streaming), stream q, output ----
    float4 pk, pkv;
    {
        float4 ck  = *(const float4*)&s_chain[d4 * 4];
        float4 ckv = *(const float4*)&s_chain[128 + d4 * 4];
        float4 ek  = *(const float4*)&s_k [g][d4 * 4];
        float4 ekv = *(const float4*)&s_kv[g][d4 * 4];
        pk  = make_float4(ck.x + ek.x,  ck.y + ek.y,  ck.z + ek.z,  ck.w + ek.w);
        pkv = make_float4(ckv.x + ekv.x, ckv.y + ekv.y,
                          ckv.z + ekv.z, ckv.w + ekv.w);
    }

    #pragma unroll 4
    for (int i = 0; i < 16; ++i) {
        const size_t off = base + (size_t)i * D_;
        float4 kk = ld_stream4(kp + off);
        float4 vv = ld_stream4(vp + off);
        float4 qq = ld_stream4(qp + off);
        float  m  = mrow[i];

        float a0 = phi(kk.x) * m, a1 = phi(kk.y) * m,
              a2 = phi(kk.z) * m, a3 = phi(kk.w) * m;
        pk.x += a0; pk.y += a1; pk.z += a2; pk.w += a3;
        pkv.x += a0 * (vv.x * m); pkv.y += a1 * (vv.y * m);
        pkv.z += a2 * (vv.z * m); pkv.w += a3 * (vv.w * m);

        float q0 = phi(qq.x), q1 = phi(qq.y),
              q2 = phi(qq.z), q3 = phi(qq.w);

        float z = q0 * pk.x + q1 * pk.y + q2 * pk.z + q3 * pk.w;
        z += __shfl_xor_sync(0xffffffffu, z, 8);
        z += __shfl_xor_sync(0xffffffffu, z, 4);
        z += __shfl_xor_sync(0xffffffffu, z, 2);
        z += __shfl_xor_sync(0xffffffffu, z, 1);
        z = (z + EPS_) * m;
        float rz = 1.0f / z;

        float4 o;
        o.x = q0 * pkv.x * rz; o.y = q1 * pkv.y * rz;
        o.z = q2 * pkv.z * rz; o.w = q3 * pkv.w * rz;
        st_stream4(op + off, o);
    }
}

// ---------------------------------------------------------------------------
extern "C" void kernel_launch(void* const* d_in, const int* in_sizes, int n_in,
                              void* d_out, int out_size)
{
    const float* q = (const float*)d_in[0];
    const float* k = (const float*)d_in[1];
    const float* v = (const float*)d_in[2];
    const float* m = (const float*)d_in[3];
    float* out = (float*)d_out;

    la_reset<<<(NBLK_ + 255) / 256, 256>>>();
    la_fused<<<NBLK_, 256>>>(q, k, v, m, out);
}

// round 10
// speedup vs baseline: 1.2475x; 1.0116x over previous
#include <cuda_runtime.h>
#include <cuda_bf16.h>

// B=4, H=16, L=8192, D=64
#define BH_    64
#define H_     16
#define L_     8192
#define D_     64
#define TILE_  256                 // positions per tile (block)
#define NT_    32                  // tiles per (b,h) chain
#define NBLK_  (BH_ * NT_)         // 2048
#define EPS_   1e-6f

// Decoupled-lookback state. flag: 0 = none, 1 = aggregate, 2 = inclusive.
__device__ int   g_ticket;
__device__ int   g_flag[NBLK_];
__device__ float g_aggr[(size_t)NBLK_ * 256];   // [128 k-sum | 128 kv-sum]
__device__ float g_incl[(size_t)NBLK_ * 256];

__device__ __forceinline__ float phi(float x) {
    return x > 0.0f ? x + 1.0f : __expf(x);
}

// evict_last load via createpolicy + cache_hint (the sm_103a-legal encoding)
__device__ __forceinline__ unsigned long long mk_evict_last_policy() {
    unsigned long long pol;
    asm("createpolicy.fractional.L2::evict_last.b64 %0, 1.0;" : "=l"(pol));
    return pol;
}
__device__ __forceinline__ float4 ld_keep4(const float* p, unsigned long long pol) {
    float4 r;
    asm("ld.global.nc.L2::cache_hint.v4.f32 {%0,%1,%2,%3}, [%4], %5;"
        : "=f"(r.x), "=f"(r.y), "=f"(r.z), "=f"(r.w) : "l"(p), "l"(pol));
    return r;
}
__device__ __forceinline__ float4 ld_stream4(const float* p) {
    float4 r;
    asm("ld.global.cs.nc.v4.f32 {%0,%1,%2,%3}, [%4];"
        : "=f"(r.x), "=f"(r.y), "=f"(r.z), "=f"(r.w) : "l"(p));
    return r;
}
__device__ __forceinline__ void st_stream4(float* p, float4 v) {
    asm volatile("st.global.cs.v4.f32 [%0], {%1,%2,%3,%4};"
                 :: "l"(p), "f"(v.x), "f"(v.y), "f"(v.z), "f"(v.w) : "memory");
}

__global__ void la_reset() {
    int i = blockIdx.x * blockDim.x + threadIdx.x;
    if (i < NBLK_) g_flag[i] = 0;
    if (i == 0) g_ticket = 0;
}

// ---------------------------------------------------------------------------
// Fused single-pass scan. Phase A loads k,v with an evict_last L2 policy so
// the phase-C re-read hits L2; phase C reads k,v,q streaming and writes output
// streaming. 6 blocks/SM to overlap per-block sync bubbles with other blocks'
// streaming. Thread map: g = t>>4 owns positions [g*16, g*16+16); d4 = t&15
// owns channel quad d4*4..d4*4+3.
// ---------------------------------------------------------------------------
__global__ void __launch_bounds__(256, 6) la_fused(
    const float* __restrict__ qp, const float* __restrict__ kp,
    const float* __restrict__ vp, const float* __restrict__ mp,
    float* __restrict__ op)
{
    __shared__ float s_k [16][128];   // group sums -> exclusive group prefixes
    __shared__ float s_kv[16][128];
    __shared__ float s_tot[256];      // tile totals   [k | kv]
    __shared__ float s_chain[256];    // chain prefix  [k | kv]
    __shared__ int   s_tile, s_msg;

    const int t = threadIdx.x;
    if (t == 0) s_tile = atomicAdd(&g_ticket, 1);
    __syncthreads();
    const int tile = s_tile;
    const int bh   = tile & (BH_ - 1);     // chain-interleaved ticket mapping
    const int ti   = tile >> 6;
    const int b    = bh >> 4;
    const int g    = t >> 4;
    const int d4   = t & 15;
    const int l0   = ti * TILE_ + g * 16;
    const size_t base = ((size_t)bh * L_ + l0) * D_ + d4 * 4;
    const float* mrow = mp + b * L_ + l0;
    const unsigned long long pol = mk_evict_last_policy();

    // ---- Phase A: group sums of masked phi(k), phi(k)*v (evict_last) ----
    float4 sk  = make_float4(0.f, 0.f, 0.f, 0.f);
    float4 skv = make_float4(0.f, 0.f, 0.f, 0.f);
    #pragma unroll 4
    for (int i = 0; i < 16; ++i) {
        float4 kk = ld_keep4(kp + base + (size_t)i * D_, pol);
        float4 vv = ld_keep4(vp + base + (size_t)i * D_, pol);
        float  m  = mrow[i];
        float a0 = phi(kk.x) * m, a1 = phi(kk.y) * m,
              a2 = phi(kk.z) * m, a3 = phi(kk.w) * m;
        sk.x += a0; sk.y += a1; sk.z += a2; sk.w += a3;
        skv.x += a0 * (vv.x * m); skv.y += a1 * (vv.y * m);
        skv.z += a2 * (vv.z * m); skv.w += a3 * (vv.w * m);
    }
    *(float4*)&s_k [g][d4 * 4] = sk;
    *(float4*)&s_kv[g][d4 * 4] = skv;
    __syncthreads();

    // ---- Intra-tile scan over the 16 groups (t<128: k, t>=128: kv) ----
    {
        float run = 0.f;
        if (t < 128) {
            const int c = t;
            #pragma unroll
            for (int g2 = 0; g2 < 16; ++g2) {
                float x = s_k[g2][c]; s_k[g2][c] = run; run += x;
            }
        } else {
            const int c = t - 128;
            #pragma unroll
            for (int g2 = 0; g2 < 16; ++g2) {
                float x = s_kv[g2][c]; s_kv[g2][c] = run; run += x;
            }
        }
        s_tot[t] = run;
        if (ti > 0) g_aggr[(size_t)tile * 256 + t] = run;
    }
    __syncthreads();
    if (ti > 0) {
        __threadfence();
        if (t == 0) atomicExch(&g_flag[tile], 1);
    }

    // ---- Decoupled lookback (single flag per tile; thread 0 polls) ----
    s_chain[t] = 0.f;
    if (ti > 0) {
        volatile int* vf = (volatile int*)g_flag;
        int p = tile - BH_;
        for (;;) {
            if (t == 0) {
                int f;
                while ((f = vf[p]) == 0) __nanosleep(64);
                s_msg = f;
            }
            __syncthreads();
            const int f = s_msg;
            __threadfence();   // acquire: order payload reads after flag read
            if (f == 2) {
                s_chain[t] += g_incl[(size_t)p * 256 + t];
                break;
            }
            s_chain[t] += g_aggr[(size_t)p * 256 + t];
            p -= BH_;
            __syncthreads();
        }
    }
    __syncthreads();

    // ---- Publish inclusive prefix for successors ----
    g_incl[(size_t)tile * 256 + t] = s_chain[t] + s_tot[t];
    __syncthreads();
    __threadfence();
    if (t == 0) atomicExch(&g_flag[tile], 2);

    // ---- Phase C: re-read own k,v from L2 (streaming), stream q, output ----
    float4 pk, pkv;
    {
        float4 ck  = *(const float4*)&s_chain[d4 * 4];
        float4 ckv = *(const float4*)&s_chain[128 + d4 * 4];
        float4 ek  = *(const float4*)&s_k [g][d4 * 4];
        float4 ekv = *(const float4*)&s_kv[g][d4 * 4];
        pk  = make_float4(ck.x + ek.x,  ck.y + ek.y,  ck.z + ek.z,  ck.w + ek.w);
        pkv = make_float4(ckv.x + ekv.x, ckv.y + ekv.y,
                          ckv.z + ekv.z, ckv.w + ekv.w);
    }

    #pragma unroll 4
    for (int i = 0; i < 16; ++i) {
        const size_t off = base + (size_t)i * D_;
        float4 kk = ld_stream4(kp + off);
        float4 vv = ld_stream4(vp + off);
        float4 qq = ld_stream4(qp + off);
        float  m  = mrow[i];

        float a0 = phi(kk.x) * m, a1 = phi(kk.y) * m,
              a2 = phi(kk.z) * m, a3 = phi(kk.w) * m;
        pk.x += a0; pk.y += a1; pk.z += a2; pk.w += a3;
        pkv.x += a0 * (vv.x * m); pkv.y += a1 * (vv.y * m);
        pkv.z += a2 * (vv.z * m); pkv.w += a3 * (vv.w * m);

        float q0 = phi(qq.x), q1 = phi(qq.y),
              q2 = phi(qq.z), q3 = phi(qq.w);

        float z = q0 * pk.x + q1 * pk.y + q2 * pk.z + q3 * pk.w;
        z += __shfl_xor_sync(0xffffffffu, z, 8);
        z += __shfl_xor_sync(0xffffffffu, z, 4);
        z += __shfl_xor_sync(0xffffffffu, z, 2);
        z += __shfl_xor_sync(0xffffffffu, z, 1);
        z = (z + EPS_) * m;
        float rz = 1.0f / z;

        float4 o;
        o.x = q0 * pkv.x * rz; o.y = q1 * pkv.y * rz;
        o.z = q2 * pkv.z * rz; o.w = q3 * pkv.w * rz;
        st_stream4(op + off, o);
    }
}

// ---------------------------------------------------------------------------
extern "C" void kernel_launch(void* const* d_in, const int* in_sizes, int n_in,
                              void* d_out, int out_size)
{
    const float* q = (const float*)d_in[0];
    const float* k = (const float*)d_in[1];
    const float* v = (const float*)d_in[2];
    const float* m = (const float*)d_in[3];
    float* out = (float*)d_out;

    la_reset<<<(NBLK_ + 255) / 256, 256>>>();
    la_fused<<<NBLK_, 256>>>(q, k, v, m, out);
}